// round 7
// baseline (speedup 1.0000x reference)
#include <cuda_runtime.h>
#include <cuda_fp16.h>
#include <stdint.h>

// Problem constants
#define NS   36      // streams
#define HH   256     // hidden
#define GWW  1024    // gate width
#define BB   32      // batch
#define TST  128     // timesteps
#define FEAT 9472    // (NS+1)*HH

#define DEPTH 4            // ring slots per warp
#define SLOT_BYTES 2048    // one stage = one k-slice (4 frags of 512 B)
#define RING_BYTES (8 * DEPTH * SLOT_BYTES)      // 65536
#define SMEM_BYTES (RING_BYTES + 8 * DEPTH * 8)  // + mbarriers = 65792

// ---------------- device scratch (static; no allocation) ----------------
// Weights in TMA-stream order, hi/lo fp16 pairs.
// Per (matmul m, stream n): 2048 frags; frag = w8g*64 + ks*4 + ctl  (w8g in [0,32)).
// Each frag = 32 lanes * 8 halves (4 hi + 4 lo) = 512 B. Warp region = 64 frags = 32 KB contiguous.
__device__ __half g_B[3u * NS * 524288u];              // 113 MB
// h buffers in A-fragment order, hi/lo: per stream 16ks*2rt*32lane*16halves = 16384 halves.
__device__ __half g_H1[2][NS][16384];
__device__ __half g_H2[2][NS][16384];
__device__ float  g_c1[NS * HH * BB];
__device__ float  g_c2[NS * HH * BB];
__device__ float  g_Wih1p[NS * GWW];                   // permuted gate order (u*4+gt)
__device__ float  g_bg1p[NS * GWW];
__device__ float  g_bg2p[NS * GWW];
__device__ float  g_featT[FEAT * BB];                  // featT[k][b]
__device__ float  g_act[BB * HH];                      // fc1 output (post-ReLU)

// ---------------- PTX helpers ----------------
__device__ __forceinline__ uint32_t smem_u32(const void* p) {
    uint32_t a;
    asm("{ .reg .u64 t; cvta.to.shared.u64 t, %1; cvt.u32.u64 %0, t; }" : "=r"(a) : "l"(p));
    return a;
}
__device__ __forceinline__ void mbar_init(uint32_t mbar, uint32_t cnt) {
    asm volatile("mbarrier.init.shared.b64 [%0], %1;" :: "r"(mbar), "r"(cnt) : "memory");
}
__device__ __forceinline__ void mbar_expect_tx(uint32_t mbar, uint32_t bytes) {
    asm volatile("mbarrier.arrive.expect_tx.shared.b64 _, [%0], %1;"
                 :: "r"(mbar), "r"(bytes) : "memory");
}
__device__ __forceinline__ void bulk_copy(uint32_t dst, const void* src, uint32_t bytes, uint32_t mbar) {
    asm volatile("cp.async.bulk.shared::cta.global.mbarrier::complete_tx::bytes [%0], [%1], %2, [%3];"
                 :: "r"(dst), "l"(src), "r"(bytes), "r"(mbar) : "memory");
}
__device__ __forceinline__ void mbar_wait(uint32_t mbar, uint32_t parity) {
    uint32_t done;
    asm volatile("{\n\t.reg .pred p;\n\t"
                 "mbarrier.try_wait.parity.acquire.cta.shared::cta.b64 p, [%1], %2;\n\t"
                 "selp.b32 %0, 1, 0, p;\n\t}"
                 : "=r"(done) : "r"(mbar), "r"(parity) : "memory");
    if (!done) {
        asm volatile("{\n\t.reg .pred P1;\n\t"
                     "W1_%=:\n\t"
                     "mbarrier.try_wait.parity.acquire.cta.shared::cta.b64 P1, [%0], %1, 0x989680;\n\t"
                     "@P1 bra.uni W2_%=;\n\t"
                     "bra.uni W1_%=;\n\t"
                     "W2_%=:\n\t}"
                     :: "r"(mbar), "r"(parity) : "memory");
    }
}
__device__ __forceinline__ void lds128v(uint4& v, uint32_t addr) {
    asm volatile("ld.shared.v4.b32 {%0,%1,%2,%3}, [%4];"
                 : "=r"(v.x), "=r"(v.y), "=r"(v.z), "=r"(v.w) : "r"(addr));
}
__device__ __forceinline__ void mma16816(float c[4],
                                         uint32_t a0, uint32_t a1, uint32_t a2, uint32_t a3,
                                         uint32_t b0, uint32_t b1) {
    asm volatile(
        "mma.sync.aligned.m16n8k16.row.col.f32.f16.f16.f32 "
        "{%0,%1,%2,%3}, {%4,%5,%6,%7}, {%8,%9}, {%0,%1,%2,%3};"
        : "+f"(c[0]), "+f"(c[1]), "+f"(c[2]), "+f"(c[3])
        : "r"(a0), "r"(a1), "r"(a2), "r"(a3), "r"(b0), "r"(b1));
}
__device__ __forceinline__ float sigf(float v) { return 1.0f / (1.0f + expf(-v)); }

// ---------------- setup kernels ----------------
// Convert big weights (Whh1, Wih2, Whh2) fp32 -> stream-ordered hi/lo fp16 fragments.
__global__ void conv_big(const float* __restrict__ Whh1,
                         const float* __restrict__ Wih2,
                         const float* __restrict__ Whh2) {
    int idx = blockIdx.x * 256 + threadIdx.x;        // 3*36*2048*32 = 7,077,888
    if (idx >= 3 * NS * 2048 * 32) return;
    int lane = idx & 31;
    int r    = idx >> 5;
    int frag = r & 2047;          // w8g*64 + ks*4 + ctl
    int r2   = r >> 11;
    int n    = r2 % NS;
    int m    = r2 / NS;
    int ctl  = frag & 3;
    int ks   = (frag >> 2) & 15;
    int w8g  = frag >> 6;         // [0,32): global warp-column index (bl*8 + w8)
    int col  = w8g * 32 + ctl * 8 + (lane >> 2);   // permuted gate-col [0,1024)
    int i4   = lane & 3;
    int u    = col >> 2;
    int gt   = col & 3;
    int g_orig = gt * 256 + u;    // original torch gate index
    const float* W = (m == 0) ? Whh1 : ((m == 1) ? Wih2 : Whh2);
    const float* src = W + ((size_t)n * GWW + g_orig) * HH + ks * 16;
    __half* dst = g_B + ((size_t)(m * NS + n) * 2048 + frag) * 256 + lane * 8;
    int kk0 = 2 * i4;
    int kks[4] = {kk0, kk0 + 1, kk0 + 8, kk0 + 9};
#pragma unroll
    for (int j = 0; j < 4; j++) {
        float v = src[kks[j]];
        __half hi = __float2half_rn(v);
        __half lo = __float2half_rn(v - __half2float(hi));
        dst[j]     = hi;
        dst[4 + j] = lo;
    }
}

// Permute Wih1 and fused biases into u*4+gt order.
__global__ void conv_small(const float* __restrict__ Wih1,
                           const float* __restrict__ bih1, const float* __restrict__ bhh1,
                           const float* __restrict__ bih2, const float* __restrict__ bhh2) {
    int idx = blockIdx.x * 256 + threadIdx.x;        // 36*1024
    if (idx >= NS * GWW) return;
    int n = idx >> 10;
    int col = idx & 1023;
    int u = col >> 2, gt = col & 3;
    int go = gt * 256 + u;
    int s = n * GWW + go;
    g_Wih1p[idx] = Wih1[s];
    g_bg1p[idx]  = bih1[s] + bhh1[s];
    g_bg2p[idx]  = bih2[s] + bhh2[s];
}

__global__ void init_kernel() {
    int idx = blockIdx.x * 256 + threadIdx.x;
    if (idx < 2 * NS * 16384 / 2) {                  // both parities
        ((uint32_t*)g_H1)[idx] = 0u;
        ((uint32_t*)g_H2)[idx] = 0u;
    }
    if (idx < NS * HH * BB) {
        g_c1[idx] = 0.f;
        g_c2[idx] = 0.f;
    }
}

__global__ void spec_kernel(const float* __restrict__ spec,
                            const float* __restrict__ Wspec,
                            const float* __restrict__ bspec) {
    int j = threadIdx.x;                             // [0,256)
    for (int b = 0; b < BB; b++) {
        float s = bspec[j];
#pragma unroll
        for (int i = 0; i < 6; i++) s += spec[b * 6 + i] * Wspec[i * HH + j];
        g_featT[(NS * HH + j) * BB + b] = s;
    }
}

// ---------------- per-step kernel: blocks [0,144) = layer1(t), [144,288) = layer2(t-1) ----------------
// 256 threads = 8 warps; warp w8 owns 32 output cols (4 ct-tiles) and a private
// 4-deep TMA ring (2 KB/slot). No cross-warp sync in the mainloop.
__global__ void __launch_bounds__(256, 2) step_kernel(int t, const float* __restrict__ x) {
    extern __shared__ __align__(128) unsigned char smem[];
    uint32_t smem_base = smem_u32(smem);

    int bid = blockIdx.x;
    bool isL2 = (bid >= 144);
    int lb = isL2 ? bid - 144 : bid;
    int st = isL2 ? t - 1 : t;
    if (st < 0 || st >= TST) return;
    int n = lb >> 2, bl = lb & 3;
    int tid = threadIdx.x, w8 = tid >> 5, lane = tid & 31;
    int w8g = bl * 8 + w8;
    int rp = st & 1, wp = rp ^ 1;

    uint32_t ringBase = smem_base + (uint32_t)w8 * (DEPTH * SLOT_BYTES);
    uint32_t mbarBase = smem_base + RING_BYTES + (uint32_t)w8 * (DEPTH * 8);

    // per-warp mbarrier init (lane 0 only; no cross-warp use)
    if (lane == 0) {
#pragma unroll
        for (int d = 0; d < DEPTH; d++) mbar_init(mbarBase + d * 8, 1);
        asm volatile("fence.proxy.async.shared::cta;" ::: "memory");
    }
    __syncwarp();

    int S = isL2 ? 32 : 16;                  // total stages (k-slices across 1 or 2 matmuls)
    int m0 = isL2 ? 1 : 0;
    const __half* Asrc0 = isL2 ? g_H1[wp][n] : g_H1[rp][n];
    const __half* Asrc1 = g_H2[rp][n];       // used by stages >=16 (isL2 only)

    // gmem byte offset of stage s for this warp
    const char* Bbase = (const char*)g_B;
    size_t warpOff0 = ((size_t)((m0 * NS) + n) * 2048 + (size_t)w8g * 64) * 512;
    size_t warpOff1 = ((size_t)(((m0 + 1) * NS) + n) * 2048 + (size_t)w8g * 64) * 512;

    // prologue: fill the ring
    if (lane == 0) {
#pragma unroll
        for (int s = 0; s < DEPTH; s++) {
            if (s < S) {
                size_t off = ((s < 16) ? warpOff0 : warpOff1) + (size_t)(s & 15) * SLOT_BYTES;
                mbar_expect_tx(mbarBase + s * 8, SLOT_BYTES);
                bulk_copy(ringBase + s * SLOT_BYTES, Bbase + off, SLOT_BYTES, mbarBase + s * 8);
            }
        }
    }

    float acc[2][4][4];
#pragma unroll
    for (int a = 0; a < 2; a++)
#pragma unroll
        for (int b = 0; b < 4; b++)
#pragma unroll
            for (int c = 0; c < 4; c++) acc[a][b][c] = 0.f;

    for (int s = 0; s < S; s++) {
        int slot = s & (DEPTH - 1);
        mbar_wait(mbarBase + slot * 8, (s >> 2) & 1);
        int ks = s & 15;
        const uint4* A = (const uint4*)((s < 16) ? Asrc0 : Asrc1);

        uint4 ahi[2], alo[2];
#pragma unroll
        for (int rt = 0; rt < 2; rt++) {
            const uint4* ap = A + ((ks * 2 + rt) * 32 + lane) * 2;
            ahi[rt] = ap[0];
            alo[rt] = ap[1];
        }
        uint4 b[4];
#pragma unroll
        for (int ctl = 0; ctl < 4; ctl++)
            lds128v(b[ctl], ringBase + slot * SLOT_BYTES + ctl * 512 + lane * 16);

#pragma unroll
        for (int ctl = 0; ctl < 4; ctl++)
#pragma unroll
            for (int rt = 0; rt < 2; rt++) {
                mma16816(acc[rt][ctl], ahi[rt].x, ahi[rt].y, ahi[rt].z, ahi[rt].w, b[ctl].x, b[ctl].y);  // Hhi*Whi
                mma16816(acc[rt][ctl], ahi[rt].x, ahi[rt].y, ahi[rt].z, ahi[rt].w, b[ctl].z, b[ctl].w);  // Hhi*Wlo
                mma16816(acc[rt][ctl], alo[rt].x, alo[rt].y, alo[rt].z, alo[rt].w, b[ctl].x, b[ctl].y);  // Hlo*Whi
            }

        // refill this slot for stage s+DEPTH (issued after the consuming MMAs in
        // program order; warp in-order issue guarantees LDS data is already in regs)
        int s2 = s + DEPTH;
        if (s2 < S && lane == 0) {
            size_t off = ((s2 < 16) ? warpOff0 : warpOff1) + (size_t)(s2 & 15) * SLOT_BYTES;
            mbar_expect_tx(mbarBase + slot * 8, SLOT_BYTES);
            bulk_copy(ringBase + slot * SLOT_BYTES, Bbase + off, SLOT_BYTES, mbarBase + slot * 8);
        }
    }

    // sg overlays the ring (all TMA traffic done; fence with syncthreads)
    __syncthreads();
    float* sg = (float*)smem;                // BB*256 floats = 32 KB <= 64 KB ring

    int g8 = lane >> 2;
    int i2 = (lane & 3) * 2;
#pragma unroll
    for (int rt = 0; rt < 2; rt++)
#pragma unroll
        for (int ctl = 0; ctl < 4; ctl++) {
            int col = w8 * 32 + ctl * 8 + i2;
            int r0 = rt * 16 + g8;
            sg[r0 * 256 + col]           = acc[rt][ctl][0];
            sg[r0 * 256 + col + 1]       = acc[rt][ctl][1];
            sg[(r0 + 8) * 256 + col]     = acc[rt][ctl][2];
            sg[(r0 + 8) * 256 + col + 1] = acc[rt][ctl][3];
        }
    __syncthreads();

    float* cbuf = isL2 ? g_c2 : g_c1;
    const float* bias = isL2 ? g_bg2p : g_bg1p;
    __half* Hout = isL2 ? g_H2[wp][n] : g_H1[wp][n];

    for (int e = tid; e < BB * 64; e += 256) {
        int b  = e & 31;
        int ul = e >> 5;                 // local unit [0,64)
        int u  = bl * 64 + ul;           // unit [0,256)
        int cb = ul * 4;
        int colg = bl * 256 + cb;        // permuted col within stream
        float ip = sg[b * 256 + cb + 0] + bias[n * GWW + colg + 0];
        float fp = sg[b * 256 + cb + 1] + bias[n * GWW + colg + 1];
        float gp = sg[b * 256 + cb + 2] + bias[n * GWW + colg + 2];
        float op = sg[b * 256 + cb + 3] + bias[n * GWW + colg + 3];
        if (!isL2) {
            float xv = x[(b * TST + st) * NS + n];
            ip += xv * g_Wih1p[n * GWW + colg + 0];
            fp += xv * g_Wih1p[n * GWW + colg + 1];
            gp += xv * g_Wih1p[n * GWW + colg + 2];
            op += xv * g_Wih1p[n * GWW + colg + 3];
        }
        float iv = sigf(ip), fv = sigf(fp), gv = tanhf(gp), ov = sigf(op);
        int ci = (n * HH + u) * BB + b;
        float cv = fv * cbuf[ci] + iv * gv;
        cbuf[ci] = cv;
        float hv = ov * tanhf(cv);

        // write h into A-fragment layout (hi + lo)
        int ks = u >> 4, kk = u & 15;
        int rt = b >> 4, rl = b & 15;
        int gg = rl & 7, hirow = rl >> 3;
        int ii = (kk & 7) >> 1, p = kk & 1, hik = kk >> 3;
        int lane2 = gg * 4 + ii;
        int j = hik * 4 + hirow * 2 + p;
        __half hi = __float2half_rn(hv);
        __half lo = __float2half_rn(hv - __half2float(hi));
        __half* hp = Hout + ((ks * 2 + rt) * 32 + lane2) * 16;
        hp[j]     = hi;
        hp[j + 8] = lo;

        if (isL2) g_featT[(n * HH + u) * BB + b] = hv;
    }
}

// ---------------- classifier ----------------
__global__ void fc1_kernel(const float* __restrict__ Wp1, const float* __restrict__ bp1) {
    int tid = threadIdx.x;
    int b = tid & 31;
    int tj = tid >> 5;                      // [0,8)
    int j = blockIdx.x * 8 + tj;            // [0,256)
    const float* ft = g_featT + b;
    const float* wc = Wp1 + j;
    float a0 = 0.f, a1 = 0.f, a2 = 0.f, a3 = 0.f;
#pragma unroll 4
    for (int k = 0; k < FEAT; k += 4) {
        a0 += ft[(k + 0) * BB] * wc[(size_t)(k + 0) * HH];
        a1 += ft[(k + 1) * BB] * wc[(size_t)(k + 1) * HH];
        a2 += ft[(k + 2) * BB] * wc[(size_t)(k + 2) * HH];
        a3 += ft[(k + 3) * BB] * wc[(size_t)(k + 3) * HH];
    }
    float acc = bp1[j] + ((a0 + a1) + (a2 + a3));
    g_act[b * HH + j] = fmaxf(acc, 0.f);
}

__global__ void fc2_kernel(const float* __restrict__ Wp2, const float* __restrict__ bp2,
                           float* __restrict__ out) {
    int tid = threadIdx.x;
    if (tid >= BB * 30) return;
    int b = tid / 30, o = tid % 30;
    float acc = bp2[o];
#pragma unroll 8
    for (int k = 0; k < HH; k++) acc += g_act[b * HH + k] * Wp2[k * 30 + o];
    out[b * 30 + o] = acc;
}

// ---------------- launch ----------------
extern "C" void kernel_launch(void* const* d_in, const int* in_sizes, int n_in,
                              void* d_out, int out_size) {
    const float* x     = (const float*)d_in[0];
    const float* spec  = (const float*)d_in[1];
    const float* Wih1  = (const float*)d_in[2];
    const float* Whh1  = (const float*)d_in[3];
    const float* bih1  = (const float*)d_in[4];
    const float* bhh1  = (const float*)d_in[5];
    const float* Wih2  = (const float*)d_in[6];
    const float* Whh2  = (const float*)d_in[7];
    const float* bih2  = (const float*)d_in[8];
    const float* bhh2  = (const float*)d_in[9];
    const float* Wspec = (const float*)d_in[10];
    const float* bspec = (const float*)d_in[11];
    const float* Wp1   = (const float*)d_in[12];
    const float* bp1   = (const float*)d_in[13];
    const float* Wp2   = (const float*)d_in[14];
    const float* bp2   = (const float*)d_in[15];
    float* out = (float*)d_out;

    static int smem_set = 0;
    if (!smem_set) {
        cudaFuncSetAttribute(step_kernel, cudaFuncAttributeMaxDynamicSharedMemorySize, SMEM_BYTES);
        smem_set = 1;
    }

    conv_big<<<27648, 256>>>(Whh1, Wih2, Whh2);
    conv_small<<<144, 256>>>(Wih1, bih1, bhh1, bih2, bhh2);
    init_kernel<<<2304, 256>>>();
    spec_kernel<<<1, 256>>>(spec, Wspec, bspec);

    for (int t = 0; t <= TST; t++)
        step_kernel<<<288, 256, SMEM_BYTES>>>(t, x);

    fc1_kernel<<<32, 256>>>(Wp1, bp1);
    fc2_kernel<<<1, 960>>>(Wp2, bp2, out);
}

// round 8
// speedup vs baseline: 1.0846x; 1.0846x over previous
#include <cuda_runtime.h>
#include <cuda_fp16.h>
#include <stdint.h>

// Problem constants
#define NS   36      // streams
#define HH   256     // hidden
#define GWW  1024    // gate width
#define BB   32      // batch
#define TST  128     // timesteps
#define FEAT 9472    // (NS+1)*HH

#define DEPTH 4            // ring slots per warp
#define SLOT_BYTES 2048    // one stage = one k-slice (4 frags of 512 B)
#define RING_BYTES (8 * DEPTH * SLOT_BYTES)      // 65536
#define SMEM_BYTES RING_BYTES

// ---------------- device scratch (static; no allocation) ----------------
// Weights in stream order, hi/lo fp16 pairs.
// Per (matmul m, stream n): 2048 frags; frag = w8g*64 + ks*4 + ctl  (w8g in [0,32)).
// Each frag = 32 lanes * 8 halves (4 hi + 4 lo) = 512 B. Warp region = 64 frags = 32 KB contiguous.
__device__ __half g_B[3u * NS * 524288u];              // 113 MB
// h buffers in A-fragment order, hi/lo: per stream 16ks*2rt*32lane*16halves = 16384 halves.
__device__ __half g_H1[2][NS][16384];
__device__ __half g_H2[2][NS][16384];
__device__ float  g_c1[NS * HH * BB];
__device__ float  g_c2[NS * HH * BB];
__device__ float  g_Wih1p[NS * GWW];                   // permuted gate order (u*4+gt)
__device__ float  g_bg1p[NS * GWW];
__device__ float  g_bg2p[NS * GWW];
__device__ float  g_featT[FEAT * BB];                  // featT[k][b]
__device__ float  g_act[BB * HH];                      // fc1 output (post-ReLU)

// ---------------- PTX helpers ----------------
__device__ __forceinline__ uint32_t smem_u32(const void* p) {
    uint32_t a;
    asm("{ .reg .u64 t; cvta.to.shared.u64 t, %1; cvt.u32.u64 %0, t; }" : "=r"(a) : "l"(p));
    return a;
}
__device__ __forceinline__ void cp_async16(uint32_t dst, const void* src) {
    asm volatile("cp.async.cg.shared.global [%0], [%1], 16;" :: "r"(dst), "l"(src) : "memory");
}
__device__ __forceinline__ void cp_commit() {
    asm volatile("cp.async.commit_group;" ::: "memory");
}
__device__ __forceinline__ void cp_wait2() {
    asm volatile("cp.async.wait_group 2;" ::: "memory");
}
__device__ __forceinline__ void lds128v(uint4& v, uint32_t addr) {
    asm volatile("ld.shared.v4.b32 {%0,%1,%2,%3}, [%4];"
                 : "=r"(v.x), "=r"(v.y), "=r"(v.z), "=r"(v.w) : "r"(addr));
}
__device__ __forceinline__ void mma16816(float c[4],
                                         uint32_t a0, uint32_t a1, uint32_t a2, uint32_t a3,
                                         uint32_t b0, uint32_t b1) {
    asm volatile(
        "mma.sync.aligned.m16n8k16.row.col.f32.f16.f16.f32 "
        "{%0,%1,%2,%3}, {%4,%5,%6,%7}, {%8,%9}, {%0,%1,%2,%3};"
        : "+f"(c[0]), "+f"(c[1]), "+f"(c[2]), "+f"(c[3])
        : "r"(a0), "r"(a1), "r"(a2), "r"(a3), "r"(b0), "r"(b1));
}
__device__ __forceinline__ float sigf(float v) { return 1.0f / (1.0f + expf(-v)); }

// ---------------- setup kernels ----------------
// Convert big weights (Whh1, Wih2, Whh2) fp32 -> stream-ordered hi/lo fp16 fragments.
__global__ void conv_big(const float* __restrict__ Whh1,
                         const float* __restrict__ Wih2,
                         const float* __restrict__ Whh2) {
    int idx = blockIdx.x * 256 + threadIdx.x;        // 3*36*2048*32 = 7,077,888
    if (idx >= 3 * NS * 2048 * 32) return;
    int lane = idx & 31;
    int r    = idx >> 5;
    int frag = r & 2047;          // w8g*64 + ks*4 + ctl
    int r2   = r >> 11;
    int n    = r2 % NS;
    int m    = r2 / NS;
    int ctl  = frag & 3;
    int ks   = (frag >> 2) & 15;
    int w8g  = frag >> 6;         // [0,32): global warp-column index
    int col  = w8g * 32 + ctl * 8 + (lane >> 2);   // permuted gate-col [0,1024)
    int i4   = lane & 3;
    int u    = col >> 2;
    int gt   = col & 3;
    int g_orig = gt * 256 + u;    // original torch gate index
    const float* W = (m == 0) ? Whh1 : ((m == 1) ? Wih2 : Whh2);
    const float* src = W + ((size_t)n * GWW + g_orig) * HH + ks * 16;
    __half* dst = g_B + ((size_t)(m * NS + n) * 2048 + frag) * 256 + lane * 8;
    int kk0 = 2 * i4;
    int kks[4] = {kk0, kk0 + 1, kk0 + 8, kk0 + 9};
#pragma unroll
    for (int j = 0; j < 4; j++) {
        float v = src[kks[j]];
        __half hi = __float2half_rn(v);
        __half lo = __float2half_rn(v - __half2float(hi));
        dst[j]     = hi;
        dst[4 + j] = lo;
    }
}

// Permute Wih1 and fused biases into u*4+gt order.
__global__ void conv_small(const float* __restrict__ Wih1,
                           const float* __restrict__ bih1, const float* __restrict__ bhh1,
                           const float* __restrict__ bih2, const float* __restrict__ bhh2) {
    int idx = blockIdx.x * 256 + threadIdx.x;        // 36*1024
    if (idx >= NS * GWW) return;
    int n = idx >> 10;
    int col = idx & 1023;
    int u = col >> 2, gt = col & 3;
    int go = gt * 256 + u;
    int s = n * GWW + go;
    g_Wih1p[idx] = Wih1[s];
    g_bg1p[idx]  = bih1[s] + bhh1[s];
    g_bg2p[idx]  = bih2[s] + bhh2[s];
}

__global__ void init_kernel() {
    int idx = blockIdx.x * 256 + threadIdx.x;
    if (idx < 2 * NS * 16384 / 2) {                  // both parities
        ((uint32_t*)g_H1)[idx] = 0u;
        ((uint32_t*)g_H2)[idx] = 0u;
    }
    if (idx < NS * HH * BB) {
        g_c1[idx] = 0.f;
        g_c2[idx] = 0.f;
    }
}

__global__ void spec_kernel(const float* __restrict__ spec,
                            const float* __restrict__ Wspec,
                            const float* __restrict__ bspec) {
    int j = threadIdx.x;                             // [0,256)
    for (int b = 0; b < BB; b++) {
        float s = bspec[j];
#pragma unroll
        for (int i = 0; i < 6; i++) s += spec[b * 6 + i] * Wspec[i * HH + j];
        g_featT[(NS * HH + j) * BB + b] = s;
    }
}

// ---------------- per-step kernel: blocks [0,144) = layer1(t), [144,288) = layer2(t-1) ----------------
// 256 threads = 8 warps; warp w8 owns 32 output cols (4 ct-tiles) and a private
// 4-deep cp.async ring (2 KB/slot). Each lane copies exactly the bytes it later
// reads, so per-thread wait_group ordering suffices: no barriers in the mainloop.
__global__ void __launch_bounds__(256, 2) step_kernel(int t, const float* __restrict__ x) {
    extern __shared__ __align__(128) unsigned char smem[];
    uint32_t smem_base = smem_u32(smem);

    int bid = blockIdx.x;
    bool isL2 = (bid >= 144);
    int lb = isL2 ? bid - 144 : bid;
    int st = isL2 ? t - 1 : t;
    if (st < 0 || st >= TST) return;
    int n = lb >> 2, bl = lb & 3;
    int tid = threadIdx.x, w8 = tid >> 5, lane = tid & 31;
    int w8g = bl * 8 + w8;
    int rp = st & 1, wp = rp ^ 1;

    uint32_t ringBase = smem_base + (uint32_t)w8 * (DEPTH * SLOT_BYTES);
    uint32_t laneOff  = (uint32_t)lane * 16;

    int S = isL2 ? 32 : 16;                  // stages (k-slices across 1 or 2 matmuls)
    int m0 = isL2 ? 1 : 0;
    const __half* Asrc0 = isL2 ? g_H1[wp][n] : g_H1[rp][n];
    const __half* Asrc1 = g_H2[rp][n];       // stages >=16 (isL2 only)

    const char* Bbase = (const char*)g_B;
    size_t warpOff0 = ((size_t)((m0 * NS) + n) * 2048 + (size_t)w8g * 64) * 512;
    size_t warpOff1 = ((size_t)(((m0 + 1) * NS) + n) * 2048 + (size_t)w8g * 64) * 512;

    // prologue: issue stages 0..2 (one commit group each)
#pragma unroll
    for (int s = 0; s < 3; s++) {
        if (s < S) {
            size_t off = ((s < 16) ? warpOff0 : warpOff1) + (size_t)(s & 15) * SLOT_BYTES;
            uint32_t dst = ringBase + (uint32_t)(s & (DEPTH - 1)) * SLOT_BYTES + laneOff;
            const char* src = Bbase + off + laneOff;
#pragma unroll
            for (int j = 0; j < 4; j++)
                cp_async16(dst + j * 512, src + j * 512);
        }
        cp_commit();
    }

    float acc[2][4][4];
#pragma unroll
    for (int a = 0; a < 2; a++)
#pragma unroll
        for (int b = 0; b < 4; b++)
#pragma unroll
            for (int c = 0; c < 4; c++) acc[a][b][c] = 0.f;

    for (int s = 0; s < S; s++) {
        int slot = s & (DEPTH - 1);
        cp_wait2();                          // stage s's group complete (per-thread)
        int ks = s & 15;
        const uint4* A = (const uint4*)((s < 16) ? Asrc0 : Asrc1);

        uint4 ahi[2], alo[2];
#pragma unroll
        for (int rt = 0; rt < 2; rt++) {
            const uint4* ap = A + ((ks * 2 + rt) * 32 + lane) * 2;
            ahi[rt] = ap[0];
            alo[rt] = ap[1];
        }
        uint4 b[4];
#pragma unroll
        for (int ctl = 0; ctl < 4; ctl++)
            lds128v(b[ctl], ringBase + slot * SLOT_BYTES + ctl * 512 + laneOff);

        // refill slot (s+3)&3 for stage s+3 (different slot than the one just read)
        int s2 = s + 3;
        if (s2 < S) {
            size_t off = ((s2 < 16) ? warpOff0 : warpOff1) + (size_t)(s2 & 15) * SLOT_BYTES;
            uint32_t dst = ringBase + (uint32_t)(s2 & (DEPTH - 1)) * SLOT_BYTES + laneOff;
            const char* src = Bbase + off + laneOff;
#pragma unroll
            for (int j = 0; j < 4; j++)
                cp_async16(dst + j * 512, src + j * 512);
        }
        cp_commit();

#pragma unroll
        for (int ctl = 0; ctl < 4; ctl++)
#pragma unroll
            for (int rt = 0; rt < 2; rt++) {
                mma16816(acc[rt][ctl], ahi[rt].x, ahi[rt].y, ahi[rt].z, ahi[rt].w, b[ctl].x, b[ctl].y);  // Hhi*Whi
                mma16816(acc[rt][ctl], ahi[rt].x, ahi[rt].y, ahi[rt].z, ahi[rt].w, b[ctl].z, b[ctl].w);  // Hhi*Wlo
                mma16816(acc[rt][ctl], alo[rt].x, alo[rt].y, alo[rt].z, alo[rt].w, b[ctl].x, b[ctl].y);  // Hlo*Whi
            }
    }

    // sg overlays the ring (all async copies drained by wait+sync)
    asm volatile("cp.async.wait_group 0;" ::: "memory");
    __syncthreads();
    float* sg = (float*)smem;                // BB*256 floats = 32 KB <= 64 KB ring

    int g8 = lane >> 2;
    int i2 = (lane & 3) * 2;
#pragma unroll
    for (int rt = 0; rt < 2; rt++)
#pragma unroll
        for (int ctl = 0; ctl < 4; ctl++) {
            int col = w8 * 32 + ctl * 8 + i2;
            int r0 = rt * 16 + g8;
            sg[r0 * 256 + col]           = acc[rt][ctl][0];
            sg[r0 * 256 + col + 1]       = acc[rt][ctl][1];
            sg[(r0 + 8) * 256 + col]     = acc[rt][ctl][2];
            sg[(r0 + 8) * 256 + col + 1] = acc[rt][ctl][3];
        }
    __syncthreads();

    float* cbuf = isL2 ? g_c2 : g_c1;
    const float* bias = isL2 ? g_bg2p : g_bg1p;
    __half* Hout = isL2 ? g_H2[wp][n] : g_H1[wp][n];

    for (int e = tid; e < BB * 64; e += 256) {
        int b  = e & 31;
        int ul = e >> 5;                 // local unit [0,64)
        int u  = bl * 64 + ul;           // unit [0,256)
        int cb = ul * 4;
        int colg = bl * 256 + cb;        // permuted col within stream
        float ip = sg[b * 256 + cb + 0] + bias[n * GWW + colg + 0];
        float fp = sg[b * 256 + cb + 1] + bias[n * GWW + colg + 1];
        float gp = sg[b * 256 + cb + 2] + bias[n * GWW + colg + 2];
        float op = sg[b * 256 + cb + 3] + bias[n * GWW + colg + 3];
        if (!isL2) {
            float xv = x[(b * TST + st) * NS + n];
            ip += xv * g_Wih1p[n * GWW + colg + 0];
            fp += xv * g_Wih1p[n * GWW + colg + 1];
            gp += xv * g_Wih1p[n * GWW + colg + 2];
            op += xv * g_Wih1p[n * GWW + colg + 3];
        }
        float iv = sigf(ip), fv = sigf(fp), gv = tanhf(gp), ov = sigf(op);
        int ci = (n * HH + u) * BB + b;
        float cv = fv * cbuf[ci] + iv * gv;
        cbuf[ci] = cv;
        float hv = ov * tanhf(cv);

        // write h into A-fragment layout (hi + lo)
        int ks = u >> 4, kk = u & 15;
        int rt = b >> 4, rl = b & 15;
        int gg = rl & 7, hirow = rl >> 3;
        int ii = (kk & 7) >> 1, p = kk & 1, hik = kk >> 3;
        int lane2 = gg * 4 + ii;
        int j = hik * 4 + hirow * 2 + p;
        __half hi = __float2half_rn(hv);
        __half lo = __float2half_rn(hv - __half2float(hi));
        __half* hp = Hout + ((ks * 2 + rt) * 32 + lane2) * 16;
        hp[j]     = hi;
        hp[j + 8] = lo;

        if (isL2) g_featT[(n * HH + u) * BB + b] = hv;
    }
}

// ---------------- classifier ----------------
__global__ void fc1_kernel(const float* __restrict__ Wp1, const float* __restrict__ bp1) {
    int tid = threadIdx.x;
    int b = tid & 31;
    int tj = tid >> 5;                      // [0,8)
    int j = blockIdx.x * 8 + tj;            // [0,256)
    const float* ft = g_featT + b;
    const float* wc = Wp1 + j;
    float a0 = 0.f, a1 = 0.f, a2 = 0.f, a3 = 0.f;
#pragma unroll 4
    for (int k = 0; k < FEAT; k += 4) {
        a0 += ft[(k + 0) * BB] * wc[(size_t)(k + 0) * HH];
        a1 += ft[(k + 1) * BB] * wc[(size_t)(k + 1) * HH];
        a2 += ft[(k + 2) * BB] * wc[(size_t)(k + 2) * HH];
        a3 += ft[(k + 3) * BB] * wc[(size_t)(k + 3) * HH];
    }
    float acc = bp1[j] + ((a0 + a1) + (a2 + a3));
    g_act[b * HH + j] = fmaxf(acc, 0.f);
}

__global__ void fc2_kernel(const float* __restrict__ Wp2, const float* __restrict__ bp2,
                           float* __restrict__ out) {
    int tid = threadIdx.x;
    if (tid >= BB * 30) return;
    int b = tid / 30, o = tid % 30;
    float acc = bp2[o];
#pragma unroll 8
    for (int k = 0; k < HH; k++) acc += g_act[b * HH + k] * Wp2[k * 30 + o];
    out[b * 30 + o] = acc;
}

// ---------------- launch ----------------
extern "C" void kernel_launch(void* const* d_in, const int* in_sizes, int n_in,
                              void* d_out, int out_size) {
    const float* x     = (const float*)d_in[0];
    const float* spec  = (const float*)d_in[1];
    const float* Wih1  = (const float*)d_in[2];
    const float* Whh1  = (const float*)d_in[3];
    const float* bih1  = (const float*)d_in[4];
    const float* bhh1  = (const float*)d_in[5];
    const float* Wih2  = (const float*)d_in[6];
    const float* Whh2  = (const float*)d_in[7];
    const float* bih2  = (const float*)d_in[8];
    const float* bhh2  = (const float*)d_in[9];
    const float* Wspec = (const float*)d_in[10];
    const float* bspec = (const float*)d_in[11];
    const float* Wp1   = (const float*)d_in[12];
    const float* bp1   = (const float*)d_in[13];
    const float* Wp2   = (const float*)d_in[14];
    const float* bp2   = (const float*)d_in[15];
    float* out = (float*)d_out;

    static int smem_set = 0;
    if (!smem_set) {
        cudaFuncSetAttribute(step_kernel, cudaFuncAttributeMaxDynamicSharedMemorySize, SMEM_BYTES);
        smem_set = 1;
    }

    conv_big<<<27648, 256>>>(Whh1, Wih2, Whh2);
    conv_small<<<144, 256>>>(Wih1, bih1, bhh1, bih2, bhh2);
    init_kernel<<<2304, 256>>>();

    // steps first so ncu's skip-5 capture lands on a step_kernel launch
    for (int t = 0; t <= TST; t++)
        step_kernel<<<288, 256, SMEM_BYTES>>>(t, x);

    spec_kernel<<<1, 256>>>(spec, Wspec, bspec);   // writes spec rows of g_featT only
    fc1_kernel<<<32, 256>>>(Wp1, bp1);
    fc2_kernel<<<1, 960>>>(Wp2, bp2, out);
}

// round 10
// speedup vs baseline: 1.0956x; 1.0101x over previous
#include <cuda_runtime.h>
#include <cuda_fp16.h>
#include <stdint.h>

// Problem constants
#define NS   36      // streams
#define HH   256     // hidden
#define GWW  1024    // gate width
#define BB   32      // batch
#define TST  128     // timesteps
#define FEAT 9472    // (NS+1)*HH

#define DEPTH 4            // ring slots per warp
#define SLOT_BYTES 2048    // one stage = one k-slice (4 frags of 512 B)
#define RING_BYTES (8 * DEPTH * SLOT_BYTES)      // 65536
#define SMEM_BYTES RING_BYTES
#define NB 288             // persistent grid size (must be <= 2 blocks/SM * SMs)

// ---------------- device scratch (static; no allocation) ----------------
// Weights in stream order, hi/lo fp16 pairs.
// Per (matmul m, stream n): 2048 frags; frag = w8g*64 + ks*4 + ctl  (w8g in [0,32)).
// Each frag = 32 lanes * 8 halves (4 hi + 4 lo) = 512 B. Warp region = 64 frags = 32 KB contiguous.
__device__ __half g_B[3u * NS * 524288u];              // 113 MB
// h buffers in A-fragment order, hi/lo: per stream 16ks*2rt*32lane*16halves = 16384 halves.
__device__ __half g_H1[2][NS][16384];
__device__ __half g_H2[2][NS][16384];
__device__ float  g_c1[NS * HH * BB];
__device__ float  g_c2[NS * HH * BB];
__device__ float  g_Wih1p[NS * GWW];                   // permuted gate order (u*4+gt)
__device__ float  g_bg1p[NS * GWW];
__device__ float  g_bg2p[NS * GWW];
__device__ float  g_featT[FEAT * BB];                  // featT[k][b]
__device__ float  g_act[BB * HH];                      // fc1 output (post-ReLU)

// grid barrier state (monotone generation survives graph replays)
__device__ unsigned g_cnt;
__device__ volatile unsigned g_gen;

// ---------------- PTX helpers ----------------
__device__ __forceinline__ uint32_t smem_u32(const void* p) {
    uint32_t a;
    asm("{ .reg .u64 t; cvta.to.shared.u64 t, %1; cvt.u32.u64 %0, t; }" : "=r"(a) : "l"(p));
    return a;
}
__device__ __forceinline__ void cp_async16(uint32_t dst, const void* src) {
    asm volatile("cp.async.cg.shared.global [%0], [%1], 16;" :: "r"(dst), "l"(src) : "memory");
}
__device__ __forceinline__ void cp_commit() {
    asm volatile("cp.async.commit_group;" ::: "memory");
}
__device__ __forceinline__ void cp_wait2() {
    asm volatile("cp.async.wait_group 2;" ::: "memory");
}
__device__ __forceinline__ void lds128v(uint4& v, uint32_t addr) {
    asm volatile("ld.shared.v4.b32 {%0,%1,%2,%3}, [%4];"
                 : "=r"(v.x), "=r"(v.y), "=r"(v.z), "=r"(v.w) : "r"(addr));
}
__device__ __forceinline__ void mma16816(float c[4],
                                         uint32_t a0, uint32_t a1, uint32_t a2, uint32_t a3,
                                         uint32_t b0, uint32_t b1) {
    asm volatile(
        "mma.sync.aligned.m16n8k16.row.col.f32.f16.f16.f32 "
        "{%0,%1,%2,%3}, {%4,%5,%6,%7}, {%8,%9}, {%0,%1,%2,%3};"
        : "+f"(c[0]), "+f"(c[1]), "+f"(c[2]), "+f"(c[3])
        : "r"(a0), "r"(a1), "r"(a2), "r"(a3), "r"(b0), "r"(b1));
}
__device__ __forceinline__ float sigf(float v) { return 1.0f / (1.0f + expf(-v)); }

// Sense-reversing grid barrier. All NB blocks must be co-resident
// (guaranteed: 2 blocks/SM by launch_bounds, NB <= 2*SMs, single wave).
__device__ __forceinline__ void grid_barrier() {
    __syncthreads();
    if (threadIdx.x == 0) {
        __threadfence();                       // publish this block's gmem writes
        unsigned old = g_gen;
        if (atomicAdd(&g_cnt, 1u) == NB - 1u) {
            g_cnt = 0u;
            __threadfence();
            g_gen = old + 1u;                  // release
        } else {
            while (g_gen == old) { }           // volatile poll (L2)
        }
    }
    __syncthreads();
}

// ---------------- setup kernels ----------------
// Convert big weights (Whh1, Wih2, Whh2) fp32 -> stream-ordered hi/lo fp16 fragments.
__global__ void conv_big(const float* __restrict__ Whh1,
                         const float* __restrict__ Wih2,
                         const float* __restrict__ Whh2) {
    int idx = blockIdx.x * 256 + threadIdx.x;        // 3*36*2048*32 = 7,077,888
    if (idx >= 3 * NS * 2048 * 32) return;
    int lane = idx & 31;
    int r    = idx >> 5;
    int frag = r & 2047;          // w8g*64 + ks*4 + ctl
    int r2   = r >> 11;
    int n    = r2 % NS;
    int m    = r2 / NS;
    int ctl  = frag & 3;
    int ks   = (frag >> 2) & 15;
    int w8g  = frag >> 6;         // [0,32): global warp-column index
    int col  = w8g * 32 + ctl * 8 + (lane >> 2);   // permuted gate-col [0,1024)
    int i4   = lane & 3;
    int u    = col >> 2;
    int gt   = col & 3;
    int g_orig = gt * 256 + u;    // original torch gate index
    const float* W = (m == 0) ? Whh1 : ((m == 1) ? Wih2 : Whh2);
    const float* src = W + ((size_t)n * GWW + g_orig) * HH + ks * 16;
    __half* dst = g_B + ((size_t)(m * NS + n) * 2048 + frag) * 256 + lane * 8;
    int kk0 = 2 * i4;
    int kks[4] = {kk0, kk0 + 1, kk0 + 8, kk0 + 9};
#pragma unroll
    for (int j = 0; j < 4; j++) {
        float v = src[kks[j]];
        __half hi = __float2half_rn(v);
        __half lo = __float2half_rn(v - __half2float(hi));
        dst[j]     = hi;
        dst[4 + j] = lo;
    }
}

// Permute Wih1 and fused biases into u*4+gt order.
__global__ void conv_small(const float* __restrict__ Wih1,
                           const float* __restrict__ bih1, const float* __restrict__ bhh1,
                           const float* __restrict__ bih2, const float* __restrict__ bhh2) {
    int idx = blockIdx.x * 256 + threadIdx.x;        // 36*1024
    if (idx >= NS * GWW) return;
    int n = idx >> 10;
    int col = idx & 1023;
    int u = col >> 2, gt = col & 3;
    int go = gt * 256 + u;
    int s = n * GWW + go;
    g_Wih1p[idx] = Wih1[s];
    g_bg1p[idx]  = bih1[s] + bhh1[s];
    g_bg2p[idx]  = bih2[s] + bhh2[s];
}

__global__ void init_kernel() {
    int idx = blockIdx.x * 256 + threadIdx.x;
    if (idx < 2 * NS * 16384 / 2) {                  // both parities
        ((uint32_t*)g_H1)[idx] = 0u;
        ((uint32_t*)g_H2)[idx] = 0u;
    }
    if (idx < NS * HH * BB) {
        g_c1[idx] = 0.f;
        g_c2[idx] = 0.f;
    }
}

// ---------------- persistent step kernel ----------------
// blocks [0,144) = layer1, [144,288) = layer2 (one step behind). 129 iterations
// with a grid barrier between them replace 129 separate launches.
// 8 warps/block; warp w8 owns 32 output cols (4 ct-tiles) and a private 4-deep
// cp.async ring (2 KB/slot). Each lane copies exactly the bytes it later reads,
// so per-thread wait_group ordering suffices inside the mainloop.
__global__ void __launch_bounds__(256, 2) steps_kernel(
    const float* __restrict__ x,
    const float* __restrict__ spec,
    const float* __restrict__ Wspec,
    const float* __restrict__ bspec) {
    extern __shared__ __align__(128) unsigned char smem[];
    uint32_t smem_base = smem_u32(smem);

    int bid = blockIdx.x;
    bool isL2 = (bid >= 144);
    int lb = isL2 ? bid - 144 : bid;
    int n = lb >> 2, bl = lb & 3;
    int tid = threadIdx.x, w8 = tid >> 5, lane = tid & 31;
    int w8g = bl * 8 + w8;

    uint32_t ringBase = smem_base + (uint32_t)w8 * (DEPTH * SLOT_BYTES);
    uint32_t laneOff  = (uint32_t)lane * 16;

    const int S = isL2 ? 32 : 16;            // stages (k-slices across 1 or 2 matmuls)
    const int m0 = isL2 ? 1 : 0;
    const char* Bbase = (const char*)g_B;
    const size_t warpOff0 = ((size_t)((m0 * NS) + n) * 2048 + (size_t)w8g * 64) * 512;
    const size_t warpOff1 = ((size_t)(((m0 + 1) * NS) + n) * 2048 + (size_t)w8g * 64) * 512;

    float* cbuf = isL2 ? g_c2 : g_c1;
    const float* bias = isL2 ? g_bg2p : g_bg1p;

    for (int t = 0; t <= TST; t++) {
        int st = isL2 ? t - 1 : t;
        if (st >= 0 && st < TST) {
            int rp = st & 1, wp = rp ^ 1;
            const __half* Asrc0 = isL2 ? g_H1[wp][n] : g_H1[rp][n];
            const __half* Asrc1 = g_H2[rp][n];   // stages >=16 (isL2 only)

            // prologue: issue stages 0..2 (one commit group each)
#pragma unroll
            for (int s = 0; s < 3; s++) {
                if (s < S) {
                    size_t off = ((s < 16) ? warpOff0 : warpOff1) + (size_t)(s & 15) * SLOT_BYTES;
                    uint32_t dst = ringBase + (uint32_t)(s & (DEPTH - 1)) * SLOT_BYTES + laneOff;
                    const char* src = Bbase + off + laneOff;
#pragma unroll
                    for (int j = 0; j < 4; j++)
                        cp_async16(dst + j * 512, src + j * 512);
                }
                cp_commit();
            }

            float acc[2][4][4];
#pragma unroll
            for (int a = 0; a < 2; a++)
#pragma unroll
                for (int b = 0; b < 4; b++)
#pragma unroll
                    for (int c = 0; c < 4; c++) acc[a][b][c] = 0.f;

            for (int s = 0; s < S; s++) {
                int slot = s & (DEPTH - 1);
                cp_wait2();                      // stage s's group complete (per-thread)
                int ks = s & 15;
                const uint4* A = (const uint4*)((s < 16) ? Asrc0 : Asrc1);

                uint4 ahi[2], alo[2];
#pragma unroll
                for (int rt = 0; rt < 2; rt++) {
                    const uint4* ap = A + ((ks * 2 + rt) * 32 + lane) * 2;
                    ahi[rt] = ap[0];
                    alo[rt] = ap[1];
                }
                uint4 b[4];
#pragma unroll
                for (int ctl = 0; ctl < 4; ctl++)
                    lds128v(b[ctl], ringBase + slot * SLOT_BYTES + ctl * 512 + laneOff);

                // refill slot (s+3)&3 for stage s+3
                int s2 = s + 3;
                if (s2 < S) {
                    size_t off = ((s2 < 16) ? warpOff0 : warpOff1) + (size_t)(s2 & 15) * SLOT_BYTES;
                    uint32_t dst = ringBase + (uint32_t)(s2 & (DEPTH - 1)) * SLOT_BYTES + laneOff;
                    const char* src = Bbase + off + laneOff;
#pragma unroll
                    for (int j = 0; j < 4; j++)
                        cp_async16(dst + j * 512, src + j * 512);
                }
                cp_commit();

#pragma unroll
                for (int ctl = 0; ctl < 4; ctl++)
#pragma unroll
                    for (int rt = 0; rt < 2; rt++) {
                        mma16816(acc[rt][ctl], ahi[rt].x, ahi[rt].y, ahi[rt].z, ahi[rt].w, b[ctl].x, b[ctl].y);  // Hhi*Whi
                        mma16816(acc[rt][ctl], ahi[rt].x, ahi[rt].y, ahi[rt].z, ahi[rt].w, b[ctl].z, b[ctl].w);  // Hhi*Wlo
                        mma16816(acc[rt][ctl], alo[rt].x, alo[rt].y, alo[rt].z, alo[rt].w, b[ctl].x, b[ctl].y);  // Hlo*Whi
                    }
            }

            // sg overlays the ring (all async copies drained by wait+sync)
            asm volatile("cp.async.wait_group 0;" ::: "memory");
            __syncthreads();
            float* sg = (float*)smem;            // BB*256 floats = 32 KB <= 64 KB ring

            int g8 = lane >> 2;
            int i2 = (lane & 3) * 2;
#pragma unroll
            for (int rt = 0; rt < 2; rt++)
#pragma unroll
                for (int ctl = 0; ctl < 4; ctl++) {
                    int col = w8 * 32 + ctl * 8 + i2;
                    int r0 = rt * 16 + g8;
                    sg[r0 * 256 + col]           = acc[rt][ctl][0];
                    sg[r0 * 256 + col + 1]       = acc[rt][ctl][1];
                    sg[(r0 + 8) * 256 + col]     = acc[rt][ctl][2];
                    sg[(r0 + 8) * 256 + col + 1] = acc[rt][ctl][3];
                }
            __syncthreads();

            __half* Hout = isL2 ? g_H2[wp][n] : g_H1[wp][n];

            for (int e = tid; e < BB * 64; e += 256) {
                int b  = e & 31;
                int ul = e >> 5;                 // local unit [0,64)
                int u  = bl * 64 + ul;           // unit [0,256)
                int cb = ul * 4;
                int colg = bl * 256 + cb;        // permuted col within stream
                float ip = sg[b * 256 + cb + 0] + bias[n * GWW + colg + 0];
                float fp = sg[b * 256 + cb + 1] + bias[n * GWW + colg + 1];
                float gp = sg[b * 256 + cb + 2] + bias[n * GWW + colg + 2];
                float op = sg[b * 256 + cb + 3] + bias[n * GWW + colg + 3];
                if (!isL2) {
                    float xv = x[(b * TST + st) * NS + n];
                    ip += xv * g_Wih1p[n * GWW + colg + 0];
                    fp += xv * g_Wih1p[n * GWW + colg + 1];
                    gp += xv * g_Wih1p[n * GWW + colg + 2];
                    op += xv * g_Wih1p[n * GWW + colg + 3];
                }
                float iv = sigf(ip), fv = sigf(fp), gv = tanhf(gp), ov = sigf(op);
                int ci = (n * HH + u) * BB + b;
                float cv = fv * cbuf[ci] + iv * gv;
                cbuf[ci] = cv;
                float hv = ov * tanhf(cv);

                // write h into A-fragment layout (hi + lo)
                int ks = u >> 4, kk = u & 15;
                int rt = b >> 4, rl = b & 15;
                int gg = rl & 7, hirow = rl >> 3;
                int ii = (kk & 7) >> 1, p = kk & 1, hik = kk >> 3;
                int lane2 = gg * 4 + ii;
                int j = hik * 4 + hirow * 2 + p;
                __half hi = __float2half_rn(hv);
                __half lo = __float2half_rn(hv - __half2float(hi));
                __half* hp = Hout + ((ks * 2 + rt) * 32 + lane2) * 16;
                hp[j]     = hi;
                hp[j + 8] = lo;

                if (isL2) g_featT[(n * HH + u) * BB + b] = hv;
            }
        } else if (!isL2 && bid == 0 && t == TST) {
            // idle final iteration of an L1 block: compute spec-dense rows of featT
            int j = tid;                         // [0,256)
            for (int b = 0; b < BB; b++) {
                float s = bspec[j];
#pragma unroll
                for (int i = 0; i < 6; i++) s += spec[b * 6 + i] * Wspec[i * HH + j];
                g_featT[(NS * HH + j) * BB + b] = s;
            }
        }

        grid_barrier();                          // publishes h(t) to all blocks
    }
}

// ---------------- classifier ----------------
__global__ void fc1_kernel(const float* __restrict__ Wp1, const float* __restrict__ bp1) {
    int tid = threadIdx.x;
    int b = tid & 31;
    int tj = tid >> 5;                      // [0,8)
    int j = blockIdx.x * 8 + tj;            // [0,256)
    const float* ft = g_featT + b;
    const float* wc = Wp1 + j;
    float a0 = 0.f, a1 = 0.f, a2 = 0.f, a3 = 0.f;
#pragma unroll 4
    for (int k = 0; k < FEAT; k += 4) {
        a0 += ft[(k + 0) * BB] * wc[(size_t)(k + 0) * HH];
        a1 += ft[(k + 1) * BB] * wc[(size_t)(k + 1) * HH];
        a2 += ft[(k + 2) * BB] * wc[(size_t)(k + 2) * HH];
        a3 += ft[(k + 3) * BB] * wc[(size_t)(k + 3) * HH];
    }
    float acc = bp1[j] + ((a0 + a1) + (a2 + a3));
    g_act[b * HH + j] = fmaxf(acc, 0.f);
}

__global__ void fc2_kernel(const float* __restrict__ Wp2, const float* __restrict__ bp2,
                           float* __restrict__ out) {
    int tid = threadIdx.x;
    if (tid >= BB * 30) return;
    int b = tid / 30, o = tid % 30;
    float acc = bp2[o];
#pragma unroll 8
    for (int k = 0; k < HH; k++) acc += g_act[b * HH + k] * Wp2[k * 30 + o];
    out[b * 30 + o] = acc;
}

// ---------------- launch ----------------
extern "C" void kernel_launch(void* const* d_in, const int* in_sizes, int n_in,
                              void* d_out, int out_size) {
    const float* x     = (const float*)d_in[0];
    const float* spec  = (const float*)d_in[1];
    const float* Wih1  = (const float*)d_in[2];
    const float* Whh1  = (const float*)d_in[3];
    const float* bih1  = (const float*)d_in[4];
    const float* bhh1  = (const float*)d_in[5];
    const float* Wih2  = (const float*)d_in[6];
    const float* Whh2  = (const float*)d_in[7];
    const float* bih2  = (const float*)d_in[8];
    const float* bhh2  = (const float*)d_in[9];
    const float* Wspec = (const float*)d_in[10];
    const float* bspec = (const float*)d_in[11];
    const float* Wp1   = (const float*)d_in[12];
    const float* bp1   = (const float*)d_in[13];
    const float* Wp2   = (const float*)d_in[14];
    const float* bp2   = (const float*)d_in[15];
    float* out = (float*)d_out;

    cudaFuncSetAttribute(steps_kernel, cudaFuncAttributeMaxDynamicSharedMemorySize, SMEM_BYTES);

    conv_big<<<27648, 256>>>(Whh1, Wih2, Whh2);
    conv_small<<<144, 256>>>(Wih1, bih1, bhh1, bih2, bhh2);
    init_kernel<<<2304, 256>>>();

    steps_kernel<<<NB, 256, SMEM_BYTES>>>(x, spec, Wspec, bspec);

    fc1_kernel<<<32, 256>>>(Wp1, bp1);
    fc2_kernel<<<1, 960>>>(Wp2, bp2, out);
}